// round 4
// baseline (speedup 1.0000x reference)
#include <cuda_runtime.h>
#include <cstdint>
#include <math_constants.h>

#define BB 16
#define NPTS 4096

// ---------------- scratch (static device globals; no allocation) ----------------
__device__ __align__(16) int   g_sidx1[BB * 512];
__device__ __align__(16) float g_xyz2[BB * 512 * 3];
__device__ __align__(16) float g_grp1[BB * 9 * 512 * 32];
__device__ __align__(16) float g_feat2[BB * 128 * 512];
__device__ __align__(16) int   g_sidx2[BB * 64];
__device__ __align__(16) float g_xyz3[BB * 64 * 3];
__device__ __align__(16) float g_grp2[BB * 131 * 64 * 64];
__device__ __align__(16) float g_h2[BB * 128 * 64 * 64];
__device__ __align__(16) float g_feat3[BB * 256 * 64];
__device__ __align__(16) int   g_sidx3[BB * 1];
__device__ __align__(16) float g_xyz4[BB * 3];
__device__ __align__(16) float g_grp3[BB * 259 * 64];
__device__ __align__(16) float g_h3[BB * 512 * 64];
__device__ __align__(16) float g_feat4[BB * 1024];
__device__ __align__(16) float g_c1[BB * 1024];
__device__ __align__(16) float g_c2[BB * 512];
__device__ __align__(16) float g_c3[BB * 128];
// duplicated weights (for f32x2 broadcast operand), per-layer offsets below
__device__ __align__(16) float g_wdup[1500000];

// offsets (floats) into g_wdup
#define WD0 0          // SA1-L2: 64x128  -> 16384
#define WD1 16384      // SA2-L1: 131x128 -> 33536
#define WD2 49920      // SA2-L2: 128x256 -> 65536
#define WD3 115456     // SA3-L1: 259x512 -> 265216
#define WD4 380672     // SA3-L2: 512x1024-> 1048576

// ---------------- small helpers ----------------
__device__ __forceinline__ uint32_t smem_u32(const void* p) {
    return (uint32_t)__cvta_generic_to_shared(p);
}
__device__ __forceinline__ void cp16(uint32_t dst, const void* src, bool v) {
    asm volatile("cp.async.ca.shared.global [%0], [%1], 16, %2;"
                 :: "r"(dst), "l"(src), "r"(v ? 16 : 0));
}
__device__ __forceinline__ void cp_commit() {
    asm volatile("cp.async.commit_group;");
}
template <int N>
__device__ __forceinline__ void cp_wait() {
    asm volatile("cp.async.wait_group %0;" :: "n"(N));
}
__device__ __forceinline__ void fma2(unsigned long long& d, unsigned long long a,
                                     unsigned long long b) {
    asm("fma.rn.f32x2 %0, %1, %2, %0;" : "+l"(d) : "l"(a), "l"(b));
}
__device__ __forceinline__ float u64lo(unsigned long long v) {
    return __uint_as_float((uint32_t)v);
}
__device__ __forceinline__ float u64hi(unsigned long long v) {
    return __uint_as_float((uint32_t)(v >> 32));
}

// ---------------- merged weight duplication: Wd[c][2o]=Wd[c][2o+1]=W[o][c] ---------
__global__ void dup_all_kernel(const float* __restrict__ w0, const float* __restrict__ w1,
                               const float* __restrict__ w2, const float* __restrict__ w3,
                               const float* __restrict__ w4, float* __restrict__ wd) {
    int i = blockIdx.x * 256 + threadIdx.x;
    const float* W;
    int Cin, Cout, off;
    if (i < 8192)        { W = w0; Cin = 64;  Cout = 128;  off = WD0; }
    else if (i < 24960)  { W = w1; Cin = 131; Cout = 128;  off = WD1; i -= 8192; }
    else if (i < 57728)  { W = w2; Cin = 128; Cout = 256;  off = WD2; i -= 24960; }
    else if (i < 190336) { W = w3; Cin = 259; Cout = 512;  off = WD3; i -= 57728; }
    else if (i < 714624) { W = w4; Cin = 512; Cout = 1024; off = WD4; i -= 190336; }
    else return;
    int c = i / Cout, o = i - c * Cout;
    float v = W[(size_t)o * Cin + c];
    float* d = g_wdup + off + (size_t)c * (2 * Cout) + 2 * o;
    d[0] = v;
    d[1] = v;
}

// ---------------- furthest point sampling (exact JAX arithmetic; REDUX reduce) -----
// xyz element (b, j, k) at xyz[b*N*xst + j*xst + k]. 512 threads.
template <int ITEMS>
__global__ void fps_kernel(const float* __restrict__ xyz, int xst, int N, int npoint,
                           int* __restrict__ out) {
    const int b = blockIdx.x;
    const float* px = xyz + (size_t)b * N * xst;
    const int tid = threadIdx.x;

    float lx[ITEMS], ly[ITEMS], lz[ITEMS], ld[ITEMS];
#pragma unroll
    for (int i = 0; i < ITEMS; i++) {
        int n = tid + i * 512;
        if (n < N) {
            lx[i] = px[n * xst + 0];
            ly[i] = px[n * xst + 1];
            lz[i] = px[n * xst + 2];
            ld[i] = 1e10f;
        } else {
            ld[i] = -1.0f;
        }
    }

    __shared__ int s_far;
    __shared__ unsigned sv[16];
    __shared__ unsigned si[16];
    if (tid == 0) s_far = 0;
    __syncthreads();

    for (int it = 0; it < npoint; it++) {
        int far = s_far;
        if (tid == 0) out[b * npoint + it] = far;
        float cx = px[far * xst + 0];
        float cy = px[far * xst + 1];
        float cz = px[far * xst + 2];

        float bv = -1.0f;
        int bi = 0;
#pragma unroll
        for (int i = 0; i < ITEMS; i++) {
            int n = tid + i * 512;
            if (n < N) {
                float dx = __fsub_rn(lx[i], cx);
                float dy = __fsub_rn(ly[i], cy);
                float dz = __fsub_rn(lz[i], cz);
                float d = __fadd_rn(__fadd_rn(__fmul_rn(dx, dx), __fmul_rn(dy, dy)),
                                    __fmul_rn(dz, dz));
                float nd = fminf(ld[i], d);
                ld[i] = nd;
                if (nd > bv) { bv = nd; bi = n; }  // ascending n -> first-max kept
            }
        }
        // dists nonneg -> float bits order-preserving
        unsigned ub = (tid < N) ? __float_as_uint(bv) : 0u;
        unsigned wmax = __reduce_max_sync(0xffffffffu, ub);
        unsigned uidx = (tid < N && ub == wmax) ? (unsigned)bi : 0xffffffffu;
        unsigned wimin = __reduce_min_sync(0xffffffffu, uidx);
        if ((tid & 31) == 0) { sv[tid >> 5] = wmax; si[tid >> 5] = wimin; }
        __syncthreads();
        if (tid < 32) {
            unsigned v2 = (tid < 16) ? sv[tid] : 0u;
            unsigned i2 = (tid < 16) ? si[tid] : 0xffffffffu;
            unsigned m2 = __reduce_max_sync(0xffffffffu, v2);
            unsigned ii = (v2 == m2) ? i2 : 0xffffffffu;
            unsigned fi = __reduce_min_sync(0xffffffffu, ii);
            if (tid == 0) s_far = (int)fi;
        }
        __syncthreads();
    }
}

// ---------------- ball query + gather/group ----------------
// xyz element (b,j,k): xyzp[b*N*xst + j*xst + k]
// feat element (b,c,j): fbase[b*f_bs + c*f_cs + j*f_js]
__global__ void bq_group_kernel(const float* __restrict__ xyzp, int xst,
                                const int* __restrict__ sidx,
                                const float* __restrict__ fbase,
                                size_t f_bs, int f_cs, int f_js,
                                float* __restrict__ new_xyz, float* __restrict__ grp,
                                int N, int S, int K, int Cf, float r2) {
    const int b = blockIdx.y, s = blockIdx.x;
    const float* px = xyzp + (size_t)b * N * xst;
    const int ci = sidx[b * S + s];
    const float cx = px[ci * xst + 0];
    const float cy = px[ci * xst + 1];
    const float cz = px[ci * xst + 2];
    const int tid = threadIdx.x;

    __shared__ int sIdx[64];

    if (tid == 0) {
        new_xyz[((size_t)b * S + s) * 3 + 0] = cx;
        new_xyz[((size_t)b * S + s) * 3 + 1] = cy;
        new_xyz[((size_t)b * S + s) * 3 + 2] = cz;
    }

    if (tid < 32) {
        int cnt = 0, first = -1;
        for (int base = 0; base < N; base += 32) {
            int j = base + tid;
            bool pred = false;
            if (j < N) {
                float dx = __fsub_rn(cx, px[j * xst + 0]);
                float dy = __fsub_rn(cy, px[j * xst + 1]);
                float dz = __fsub_rn(cz, px[j * xst + 2]);
                float d2 = __fadd_rn(__fadd_rn(__fmul_rn(dx, dx), __fmul_rn(dy, dy)),
                                     __fmul_rn(dz, dz));
                pred = (d2 < r2);
            }
            unsigned m = __ballot_sync(0xffffffffu, pred);
            if (first < 0 && m) first = base + __ffs(m) - 1;
            if (pred) {
                int pos = cnt + __popc(m & ((1u << tid) - 1u));
                if (pos < K) sIdx[pos] = j;
            }
            cnt += __popc(m);
            if (cnt >= K) break;
        }
        int fillv = (first < 0) ? 0 : first;
        for (int k = cnt + tid; k < K; k += 32) sIdx[k] = fillv;
    }
    __syncthreads();

    const int C = 3 + Cf;
    const size_t SK = (size_t)S * K;
    const size_t pbase = (size_t)s * K;
    for (int e = tid; e < C * K; e += blockDim.x) {
        int ch = e / K, k = e - ch * K;
        int j = sIdx[k];
        float v;
        if (ch == 0)      v = __fsub_rn(px[j * xst + 0], cx);
        else if (ch == 1) v = __fsub_rn(px[j * xst + 1], cy);
        else if (ch == 2) v = __fsub_rn(px[j * xst + 2], cz);
        else              v = fbase[(size_t)b * f_bs + (size_t)(ch - 3) * f_cs +
                                    (size_t)j * f_js];
        grp[((size_t)b * C + ch) * SK + pbase + k] = v;
    }
}

// ---------------- fused SA1: (9->64 conv+BN+ReLU) -> (64->128 GEMM+BN+ReLU+max32) --
// grp: [B][9][16384]; Wd: dup weights [64][256]; out: feat2 [B][128][512]
// Per block: p-tile of 128 points. h rows computed on the fly per 8-row K-chunk.
__global__ __launch_bounds__(256, 2) void sa1_fused_kernel(
    const float* __restrict__ grp,
    const float* __restrict__ W0, const float* __restrict__ g0,
    const float* __restrict__ b0,
    const float* __restrict__ Wd, const float* __restrict__ g1,
    const float* __restrict__ b1, float* __restrict__ out) {
    const int P = 16384, S = 512, Cout = 128;
    __shared__ float grp_s[9][128];
    __shared__ float w0s[64 * 9];
    __shared__ float g0s[64], b0s[64];
    __shared__ float hs[2][8][128];
    __shared__ float ws[2][8][264];

    const int b = blockIdx.z;
    const int p0 = blockIdx.x * 128;
    const int tid = threadIdx.x;
    const int w = tid >> 5, l = tid & 31;
    const int warp_o = (w & 3) * 32;
    const int warp_p = (w >> 2) * 64;
    const int ofs = warp_o + ((l >> 3) << 2);
    const int pfs = warp_p + ((l & 7) << 2);

    // load grp tile + layer-1 params
    const float* gb = grp + (size_t)b * 9 * P + p0;
    for (int e = tid; e < 9 * 128; e += 256) {
        int c = e >> 7, p = e & 127;
        grp_s[c][p] = gb[(size_t)c * P + p];
    }
    for (int e = tid; e < 576; e += 256) w0s[e] = W0[e];
    if (tid < 64) { g0s[tid] = g0[tid]; b0s[tid] = b0[tid]; }

    // stage ws chunk 0
    auto stage_w = [&](int c0, int buf) {
#pragma unroll
        for (int i = 0; i < 2; i++) {
            int e = tid + i * 256;
            int k = e >> 6, w4 = (e & 63) * 4;
            cp16(smem_u32(&ws[buf][k][w4]), Wd + (size_t)(c0 + k) * 256 + w4, true);
        }
    };
    stage_w(0, 0);
    cp_commit();
    __syncthreads();

    // compute h rows [c0, c0+8) into hs[buf]
    auto calc_h = [&](int c0, int buf) {
#pragma unroll
        for (int i = 0; i < 4; i++) {
            int e = tid + i * 256;
            int r = e >> 7, p = e & 127;
            int o = c0 + r;
            float a = 0.f;
#pragma unroll
            for (int c = 0; c < 9; c++) a = fmaf(w0s[o * 9 + c], grp_s[c][p], a);
            hs[buf][r][p] = fmaxf(fmaf(a, g0s[o], b0s[o]), 0.f);
        }
    };
    calc_h(0, 0);

    unsigned long long acc2[8][4];
#pragma unroll
    for (int i = 0; i < 8; i++)
#pragma unroll
        for (int j = 0; j < 4; j++) acc2[i][j] = 0ull;

    for (int c = 0; c < 8; c++) {
        if (c < 7) {
            stage_w((c + 1) * 8, (c + 1) & 1);
            cp_commit();
            cp_wait<1>();
        } else {
            cp_wait<0>();
        }
        __syncthreads();

        const float(*wsb)[264] = ws[c & 1];
        const float(*xsb)[128] = hs[c & 1];
#pragma unroll
        for (int k = 0; k < 8; k++) {
            ulonglong2 a01 = *(const ulonglong2*)&wsb[k][2 * ofs];
            ulonglong2 a23 = *(const ulonglong2*)&wsb[k][2 * ofs + 4];
            ulonglong2 a45 = *(const ulonglong2*)&wsb[k][2 * (ofs + 16)];
            ulonglong2 a67 = *(const ulonglong2*)&wsb[k][2 * (ofs + 16) + 4];
            ulonglong2 b01 = *(const ulonglong2*)&xsb[k][pfs];
            ulonglong2 b23 = *(const ulonglong2*)&xsb[k][pfs + 32];
            unsigned long long av[8] = {a01.x, a01.y, a23.x, a23.y,
                                        a45.x, a45.y, a67.x, a67.y};
            unsigned long long bv[4] = {b01.x, b01.y, b23.x, b23.y};
#pragma unroll
            for (int i = 0; i < 8; i++)
#pragma unroll
                for (int j = 0; j < 4; j++) fma2(acc2[i][j], av[i], bv[j]);
        }
        if (c < 7) calc_h((c + 1) * 8, (c + 1) & 1);
        __syncthreads();
    }

    // epilogue: BN + ReLU + max over K=32 (one warp-half per group)
#pragma unroll
    for (int i = 0; i < 8; i++) {
        int o = ofs + ((i < 4) ? i : (12 + i));
        float gv = g1[o], bb = b1[o];
        float vf[8];
#pragma unroll
        for (int j = 0; j < 4; j++) {
            vf[2 * j]     = fmaxf(fmaf(u64lo(acc2[i][j]), gv, bb), 0.f);
            vf[2 * j + 1] = fmaxf(fmaf(u64hi(acc2[i][j]), gv, bb), 0.f);
        }
        float m0 = fmaxf(fmaxf(vf[0], vf[1]), fmaxf(vf[2], vf[3]));
        float m1 = fmaxf(fmaxf(vf[4], vf[5]), fmaxf(vf[6], vf[7]));
#pragma unroll
        for (int off = 1; off < 8; off <<= 1) {
            m0 = fmaxf(m0, __shfl_xor_sync(0xffffffffu, m0, off));
            m1 = fmaxf(m1, __shfl_xor_sync(0xffffffffu, m1, off));
        }
        if ((l & 7) == 0) {
            int pg = p0 + warp_p;
            out[((size_t)b * Cout + o) * S + (pg >> 5)] = m0;
            out[((size_t)b * Cout + o) * S + ((pg + 32) >> 5)] = m1;
        }
    }
}

// ---------------- f32x2 SGEMM: 128o x 128p tile, K-chunk 8, double-buffered --------
template <int MAXPOOL>
__global__ __launch_bounds__(256, 2) void sgemm_kernel(
    const float* __restrict__ x, const float* __restrict__ Wd,
    const float* __restrict__ g, const float* __restrict__ bi,
    float* __restrict__ out, int Cin, int Cout, int P, int S, int K) {
    __shared__ float ws[2][8][264];
    __shared__ float xs[2][8][128];

    const int b = blockIdx.z;
    const int o0 = blockIdx.y * 128;
    const int p0 = blockIdx.x * 128;
    const int tid = threadIdx.x;
    const int w = tid >> 5, l = tid & 31;
    const int warp_o = (w & 3) * 32;
    const int warp_p = (w >> 2) * 64;
    const int ofs = warp_o + ((l >> 3) << 2);
    const int pfs = warp_p + ((l & 7) << 2);

    const float* xb = x + (size_t)b * Cin * P;
    const int twoC = 2 * Cout;

    unsigned long long acc2[8][4];
#pragma unroll
    for (int i = 0; i < 8; i++)
#pragma unroll
        for (int j = 0; j < 4; j++) acc2[i][j] = 0ull;

    const int nch = (Cin + 7) >> 3;

    auto stage = [&](int c0, int buf) {
#pragma unroll
        for (int i = 0; i < 2; i++) {
            int e = tid + i * 256;
            int k = e >> 6, w4 = (e & 63) * 4;
            int cc = c0 + k;
            bool v = cc < Cin;
            const float* src = v ? (Wd + (size_t)cc * twoC + 2 * o0 + w4) : Wd;
            cp16(smem_u32(&ws[buf][k][w4]), src, v);
        }
        {
            int k = tid >> 5, p4 = (tid & 31) * 4;
            int cc = c0 + k;
            bool v = (cc < Cin) && (p0 + p4 < P);
            const float* src = v ? (xb + (size_t)cc * P + p0 + p4) : xb;
            cp16(smem_u32(&xs[buf][k][p4]), src, v);
        }
    };

    stage(0, 0);
    cp_commit();

    for (int c = 0; c < nch; c++) {
        if (c + 1 < nch) {
            stage((c + 1) * 8, (c + 1) & 1);
            cp_commit();
            cp_wait<1>();
        } else {
            cp_wait<0>();
        }
        __syncthreads();

        const float(*wsb)[264] = ws[c & 1];
        const float(*xsb)[128] = xs[c & 1];
#pragma unroll
        for (int k = 0; k < 8; k++) {
            ulonglong2 a01 = *(const ulonglong2*)&wsb[k][2 * ofs];
            ulonglong2 a23 = *(const ulonglong2*)&wsb[k][2 * ofs + 4];
            ulonglong2 a45 = *(const ulonglong2*)&wsb[k][2 * (ofs + 16)];
            ulonglong2 a67 = *(const ulonglong2*)&wsb[k][2 * (ofs + 16) + 4];
            ulonglong2 b01 = *(const ulonglong2*)&xsb[k][pfs];
            ulonglong2 b23 = *(const ulonglong2*)&xsb[k][pfs + 32];
            unsigned long long av[8] = {a01.x, a01.y, a23.x, a23.y,
                                        a45.x, a45.y, a67.x, a67.y};
            unsigned long long bv[4] = {b01.x, b01.y, b23.x, b23.y};
#pragma unroll
            for (int i = 0; i < 8; i++)
#pragma unroll
                for (int j = 0; j < 4; j++) fma2(acc2[i][j], av[i], bv[j]);
        }
        __syncthreads();
    }

#pragma unroll
    for (int i = 0; i < 8; i++) {
        int o = o0 + ofs + ((i < 4) ? i : (12 + i));
        float gv = g[o], bb = bi[o];
        float vf[8];
#pragma unroll
        for (int j = 0; j < 4; j++) {
            vf[2 * j]     = fmaxf(fmaf(u64lo(acc2[i][j]), gv, bb), 0.f);
            vf[2 * j + 1] = fmaxf(fmaf(u64hi(acc2[i][j]), gv, bb), 0.f);
        }
        if (MAXPOOL == 0) {
            float* ob = out + (size_t)b * Cout * P + (size_t)o * P;
            if (p0 + pfs < P) {
                float4 v0 = make_float4(vf[0], vf[1], vf[2], vf[3]);
                *(float4*)&ob[p0 + pfs] = v0;
            }
            if (p0 + pfs + 32 < P) {
                float4 v1 = make_float4(vf[4], vf[5], vf[6], vf[7]);
                *(float4*)&ob[p0 + pfs + 32] = v1;
            }
        } else {
            if (K == 64) {
                float m = vf[0];
#pragma unroll
                for (int j = 1; j < 8; j++) m = fmaxf(m, vf[j]);
#pragma unroll
                for (int off = 1; off < 8; off <<= 1)
                    m = fmaxf(m, __shfl_xor_sync(0xffffffffu, m, off));
                if ((l & 7) == 0) {
                    int pg = p0 + warp_p;
                    if (pg < P)
                        out[((size_t)b * Cout + o) * S + (pg >> 6)] = m;
                }
            } else {  // K == 32
                float m0 = fmaxf(fmaxf(vf[0], vf[1]), fmaxf(vf[2], vf[3]));
                float m1 = fmaxf(fmaxf(vf[4], vf[5]), fmaxf(vf[6], vf[7]));
#pragma unroll
                for (int off = 1; off < 8; off <<= 1) {
                    m0 = fmaxf(m0, __shfl_xor_sync(0xffffffffu, m0, off));
                    m1 = fmaxf(m1, __shfl_xor_sync(0xffffffffu, m1, off));
                }
                if ((l & 7) == 0) {
                    int pg = p0 + warp_p;
                    if (pg < P)
                        out[((size_t)b * Cout + o) * S + (pg >> 5)] = m0;
                    if (pg + 32 < P)
                        out[((size_t)b * Cout + o) * S + ((pg + 32) >> 5)] = m1;
                }
            }
        }
    }
}

// ---------------- dense layer on [B, Cin] vectors (classifier head) ----------------
__global__ void dense_kernel(const float* __restrict__ x, const float* __restrict__ W,
                             const float* __restrict__ g, const float* __restrict__ bi,
                             float* __restrict__ out, int Cin, int Cout, int do_relu) {
    const int b = blockIdx.x;
    const int o = blockIdx.y * 8 + (threadIdx.x >> 5);
    const int lane = threadIdx.x & 31;
    if (o >= Cout) return;
    const float* xb = x + (size_t)b * Cin;
    float acc = 0.f;
    for (int c = lane; c < Cin; c += 32)
        acc = fmaf(W[(size_t)o * Cin + c], xb[c], acc);
#pragma unroll
    for (int off = 16; off; off >>= 1)
        acc += __shfl_xor_sync(0xffffffffu, acc, off);
    if (lane == 0) {
        float v = g ? fmaf(acc, g[o], bi[o]) : (acc + bi[o]);
        if (do_relu) v = fmaxf(v, 0.f);
        out[(size_t)b * Cout + o] = v;
    }
}

// ---------------- launch ----------------
extern "C" void kernel_launch(void* const* d_in, const int* in_sizes, int n_in,
                              void* d_out, int out_size) {
    const float* pc = (const float*)d_in[0];
    const float* saw[3][2];
    const float* sag[3][2];
    const float* sab[3][2];
    for (int sm = 0; sm < 3; sm++)
        for (int l = 0; l < 2; l++) {
            int base = 1 + sm * 6 + l * 3;
            saw[sm][l] = (const float*)d_in[base + 0];
            sag[sm][l] = (const float*)d_in[base + 1];
            sab[sm][l] = (const float*)d_in[base + 2];
        }
    const float* clsw[4];
    const float* clsg[3];
    const float* clsb[4];
    for (int l = 0; l < 3; l++) {
        clsw[l] = (const float*)d_in[19 + l * 3 + 0];
        clsg[l] = (const float*)d_in[19 + l * 3 + 1];
        clsb[l] = (const float*)d_in[19 + l * 3 + 2];
    }
    clsw[3] = (const float*)d_in[28];
    clsb[3] = (const float*)d_in[29];

    float *xyz2, *grp1, *feat2, *xyz3, *grp2, *h2, *feat3;
    float *xyz4, *grp3, *h3, *feat4, *c1, *c2, *c3, *wdup;
    int *sidx1, *sidx2, *sidx3;
    cudaGetSymbolAddress((void**)&sidx1, g_sidx1);
    cudaGetSymbolAddress((void**)&xyz2, g_xyz2);
    cudaGetSymbolAddress((void**)&grp1, g_grp1);
    cudaGetSymbolAddress((void**)&feat2, g_feat2);
    cudaGetSymbolAddress((void**)&sidx2, g_sidx2);
    cudaGetSymbolAddress((void**)&xyz3, g_xyz3);
    cudaGetSymbolAddress((void**)&grp2, g_grp2);
    cudaGetSymbolAddress((void**)&h2, g_h2);
    cudaGetSymbolAddress((void**)&feat3, g_feat3);
    cudaGetSymbolAddress((void**)&sidx3, g_sidx3);
    cudaGetSymbolAddress((void**)&xyz4, g_xyz4);
    cudaGetSymbolAddress((void**)&grp3, g_grp3);
    cudaGetSymbolAddress((void**)&h3, g_h3);
    cudaGetSymbolAddress((void**)&feat4, g_feat4);
    cudaGetSymbolAddress((void**)&c1, g_c1);
    cudaGetSymbolAddress((void**)&c2, g_c2);
    cudaGetSymbolAddress((void**)&c3, g_c3);
    cudaGetSymbolAddress((void**)&wdup, g_wdup);

    // merged weight duplication
    dup_all_kernel<<<(714624 + 255) / 256, 256>>>(saw[0][1], saw[1][0], saw[1][1],
                                                  saw[2][0], saw[2][1], wdup);

    // ---- SA1: N=4096 -> S=512, K=32, r=0.1, C: 9 -> 64 -> 128 ----
    fps_kernel<8><<<BB, 512>>>(pc, 9, NPTS, 512, sidx1);
    bq_group_kernel<<<dim3(512, BB), 256>>>(pc, 9, sidx1, pc + 3,
                                            (size_t)NPTS * 9, 1, 9,
                                            xyz2, grp1, NPTS, 512, 32, 6,
                                            (float)(0.1 * 0.1));
    sa1_fused_kernel<<<dim3(16384 / 128, 1, BB), 256>>>(
        grp1, saw[0][0], sag[0][0], sab[0][0],
        wdup + WD0, sag[0][1], sab[0][1], feat2);

    // ---- SA2: N=512 -> S=64, K=64, r=0.2, C: 131 -> 128 -> 256 ----
    fps_kernel<1><<<BB, 512>>>(xyz2, 3, 512, 64, sidx2);
    bq_group_kernel<<<dim3(64, BB), 256>>>(xyz2, 3, sidx2, feat2,
                                           (size_t)128 * 512, 512, 1,
                                           xyz3, grp2, 512, 64, 64, 128,
                                           (float)(0.2 * 0.2));
    sgemm_kernel<0><<<dim3(4096 / 128, 1, BB), 256>>>(
        grp2, wdup + WD1, sag[1][0], sab[1][0], h2, 131, 128, 4096, 0, 0);
    sgemm_kernel<1><<<dim3(4096 / 128, 2, BB), 256>>>(
        h2, wdup + WD2, sag[1][1], sab[1][1], feat3, 128, 256, 4096, 64, 64);

    // ---- SA3: N=64 -> S=1, K=64, r=0.4, C: 259 -> 512 -> 1024 ----
    fps_kernel<1><<<BB, 512>>>(xyz3, 3, 64, 1, sidx3);
    bq_group_kernel<<<dim3(1, BB), 256>>>(xyz3, 3, sidx3, feat3,
                                          (size_t)256 * 64, 64, 1,
                                          xyz4, grp3, 64, 1, 64, 256,
                                          (float)(0.4 * 0.4));
    sgemm_kernel<0><<<dim3(1, 4, BB), 256>>>(
        grp3, wdup + WD3, sag[2][0], sab[2][0], h3, 259, 512, 64, 0, 0);
    sgemm_kernel<1><<<dim3(1, 8, BB), 256>>>(
        h3, wdup + WD4, sag[2][1], sab[2][1], feat4, 512, 1024, 64, 1, 64);

    // ---- classifier head on [B, 1024] ----
    dense_kernel<<<dim3(BB, 1024 / 8), 256>>>(feat4, clsw[0], clsg[0], clsb[0], c1, 1024, 1024, 1);
    dense_kernel<<<dim3(BB, 512 / 8), 256>>>(c1, clsw[1], clsg[1], clsb[1], c2, 1024, 512, 1);
    dense_kernel<<<dim3(BB, 128 / 8), 256>>>(c2, clsw[2], clsg[2], clsb[2], c3, 512, 128, 1);
    dense_kernel<<<dim3(BB, (63 + 7) / 8), 256>>>(c3, clsw[3], nullptr, clsb[3],
                                                  (float*)d_out, 128, 63, 0);
}